// round 1
// baseline (speedup 1.0000x reference)
#include <cuda_runtime.h>
#include <cuda_bf16.h>
#include <cstdint>

// Problem constants
#define NN   50000
#define EE   800000
#define HH   4
#define CC   64
#define DD   4
#define FOUT 256   // H*C

// ---------------- scratch (device globals; no allocation allowed) ----------
__device__ __align__(16) float g_h[(size_t)NN * FOUT];    // message features [N,256]
__device__ __align__(16) float g_x2[(size_t)NN * CC];     // layer-1 output  [N,64]
__device__ __align__(16) float g_asrc[NN * HH];
__device__ __align__(16) float g_adst[NN * HH];
__device__ __align__(16) float g_vsrc[128 * HH];
__device__ __align__(16) float g_vdst[128 * HH];
__device__ int g_count[NN];
__device__ int g_off[NN];
__device__ int g_rowptr[NN + 1];
__device__ int g_csr[EE];
__device__ int g_is64;

__device__ __forceinline__ float lrelu(float v, float s) { return v >= 0.f ? v : s * v; }

__device__ __forceinline__ int edge_idx(const void* ei, size_t i, int is64) {
    return is64 ? (int)((const long long*)ei)[i] : ((const int*)ei)[i];
}

// ---------------- dtype detection: int64 vs int32 edge_index ---------------
__global__ void k_detect(const int* ei_words) {
    if (threadIdx.x == 0 && blockIdx.x == 0) {
        int nz = 0;
        for (int i = 0; i < 64; i++)
            if (ei_words[2 * i + 1] != 0) nz++;
        g_is64 = (nz == 0) ? 1 : 0;
    }
}

__global__ void k_zero_count() {
    int i = blockIdx.x * blockDim.x + threadIdx.x;
    if (i < NN) g_count[i] = 0;
}

__global__ void k_hist(const void* ei) {
    int e = blockIdx.x * blockDim.x + threadIdx.x;
    if (e >= EE) return;
    int dst = edge_idx(ei, (size_t)EE + e, g_is64);
    atomicAdd(&g_count[dst], 1);
}

// single-block hierarchical exclusive scan over g_count -> g_rowptr, g_off
__global__ void k_scan() {
    __shared__ int part[1024];
    const int n = NN;
    int tid = threadIdx.x;
    int chunk = (n + 1023) >> 10;
    int s0 = tid * chunk;
    int s1 = min(s0 + chunk, n);
    int sum = 0;
    for (int i = s0; i < s1; i++) sum += g_count[i];
    part[tid] = sum;
    __syncthreads();
    for (int off = 1; off < 1024; off <<= 1) {
        int v = (tid >= off) ? part[tid - off] : 0;
        __syncthreads();
        part[tid] += v;
        __syncthreads();
    }
    int total = part[1023];
    int prefix = (tid == 0) ? 0 : part[tid - 1];
    int run = prefix;
    for (int i = s0; i < s1; i++) {
        g_rowptr[i] = run;
        g_off[i] = run;
        run += g_count[i];
    }
    if (tid == 0) g_rowptr[n] = total;
}

__global__ void k_scatter(const void* ei) {
    int e = blockIdx.x * blockDim.x + threadIdx.x;
    if (e >= EE) return;
    int is64 = g_is64;
    int src = edge_idx(ei, (size_t)e, is64);
    int dst = edge_idx(ei, (size_t)EE + e, is64);
    int pos = atomicAdd(&g_off[dst], 1);
    g_csr[pos] = src;
}

// ---------------- combine A with att vectors: vsrc[f,h] = sum_d A[f,h,d]*att_src[h,d]
__global__ void k_combine(const float* __restrict__ A, const float* __restrict__ as,
                          const float* __restrict__ ad, int fin) {
    int t = blockIdx.x * blockDim.x + threadIdx.x;
    if (t < fin * HH) {
        int f = t >> 2, h = t & 3;
        float s1 = 0.f, s2 = 0.f;
        #pragma unroll
        for (int d = 0; d < DD; d++) {
            float a = A[f * (HH * DD) + h * DD + d];
            s1 += a * as[h * DD + d];
            s2 += a * ad[h * DD + d];
        }
        g_vsrc[f * HH + h] = s1;
        g_vdst[f * HH + h] = s2;
    }
}

// ---------------- fused GEMM: h = x@W [N,256], alpha = x@vsrc / x@vdst [N,4]
template <int FIN>
__global__ __launch_bounds__(256) void k_gemm(const float* __restrict__ x,
                                              const float* __restrict__ W,
                                              float* __restrict__ hout,
                                              float* __restrict__ asrc,
                                              float* __restrict__ adst, int n) {
    __shared__ float xs[32][FIN];
    int row0 = blockIdx.x * 32;
    int tid = threadIdx.x;
    for (int idx = tid; idx < 32 * FIN; idx += 256) {
        int r = idx / FIN, k = idx - r * FIN;
        int row = row0 + r;
        xs[r][k] = (row < n) ? x[(size_t)row * FIN + k] : 0.f;
    }
    __syncthreads();

    float acc[32];
    #pragma unroll
    for (int r = 0; r < 32; r++) acc[r] = 0.f;
    const float* Wc = W + tid;
    #pragma unroll 4
    for (int k = 0; k < FIN; k++) {
        float w = Wc[(size_t)k * FOUT];
        #pragma unroll
        for (int r = 0; r < 32; r++) acc[r] = fmaf(xs[r][k], w, acc[r]);
    }
    #pragma unroll
    for (int r = 0; r < 32; r++) {
        int row = row0 + r;
        if (row < n) hout[(size_t)row * FOUT + tid] = acc[r];
    }

    // alpha: 256 threads = 32 rows x 8 (4 src-heads, 4 dst-heads)
    {
        int r = tid >> 3;
        int q = tid & 7;
        int h = q & 3;
        const float* v = (q < 4) ? g_vsrc : g_vdst;
        int row = row0 + r;
        if (row < n) {
            float s = 0.f;
            #pragma unroll 4
            for (int k = 0; k < FIN; k++) s = fmaf(xs[r][k], v[k * HH + h], s);
            ((q < 4) ? asrc : adst)[row * HH + h] = s;
        }
    }
}

// ---------------- per-dst-node softmax + weighted aggregation (1 warp/node)
__global__ __launch_bounds__(256) void k_aggr(const float* __restrict__ hf,
                                              const float* __restrict__ asrc,
                                              const float* __restrict__ adst,
                                              const float* __restrict__ bias,
                                              float* __restrict__ out, int n) {
    int node = (blockIdx.x * blockDim.x + threadIdx.x) >> 5;
    int lane = threadIdx.x & 31;
    if (node >= n) return;

    int base = g_rowptr[node];
    int deg = g_rowptr[node + 1] - base;

    float4 ad = *(const float4*)(adst + (size_t)node * 4);

    // pass 1: per-head max
    float m0 = -1e30f, m1 = -1e30f, m2 = -1e30f, m3 = -1e30f;
    for (int i = lane; i < deg; i += 32) {
        int s = g_csr[base + i];
        float4 as = *(const float4*)(asrc + (size_t)s * 4);
        m0 = fmaxf(m0, lrelu(as.x + ad.x, 0.2f));
        m1 = fmaxf(m1, lrelu(as.y + ad.y, 0.2f));
        m2 = fmaxf(m2, lrelu(as.z + ad.z, 0.2f));
        m3 = fmaxf(m3, lrelu(as.w + ad.w, 0.2f));
    }
    #pragma unroll
    for (int o = 16; o; o >>= 1) {
        m0 = fmaxf(m0, __shfl_xor_sync(0xffffffffu, m0, o));
        m1 = fmaxf(m1, __shfl_xor_sync(0xffffffffu, m1, o));
        m2 = fmaxf(m2, __shfl_xor_sync(0xffffffffu, m2, o));
        m3 = fmaxf(m3, __shfl_xor_sync(0xffffffffu, m3, o));
    }

    // pass 2: per-head denom
    float d0 = 0.f, d1 = 0.f, d2 = 0.f, d3 = 0.f;
    for (int i = lane; i < deg; i += 32) {
        int s = g_csr[base + i];
        float4 as = *(const float4*)(asrc + (size_t)s * 4);
        d0 += __expf(lrelu(as.x + ad.x, 0.2f) - m0);
        d1 += __expf(lrelu(as.y + ad.y, 0.2f) - m1);
        d2 += __expf(lrelu(as.z + ad.z, 0.2f) - m2);
        d3 += __expf(lrelu(as.w + ad.w, 0.2f) - m3);
    }
    #pragma unroll
    for (int o = 16; o; o >>= 1) {
        d0 += __shfl_xor_sync(0xffffffffu, d0, o);
        d1 += __shfl_xor_sync(0xffffffffu, d1, o);
        d2 += __shfl_xor_sync(0xffffffffu, d2, o);
        d3 += __shfl_xor_sync(0xffffffffu, d3, o);
    }
    float i0 = d0 > 0.f ? 1.f / d0 : 0.f;
    float i1 = d1 > 0.f ? 1.f / d1 : 0.f;
    float i2 = d2 > 0.f ? 1.f / d2 : 0.f;
    float i3 = d3 > 0.f ? 1.f / d3 : 0.f;

    // pass 3: weighted message accumulation
    float acc[8] = {0.f, 0.f, 0.f, 0.f, 0.f, 0.f, 0.f, 0.f};
    for (int ib = 0; ib < deg; ib += 32) {
        int rem = min(32, deg - ib);
        int sl = 0;
        float w0 = 0.f, w1 = 0.f, w2 = 0.f, w3 = 0.f;
        if (lane < rem) {
            sl = g_csr[base + ib + lane];
            float4 as = *(const float4*)(asrc + (size_t)sl * 4);
            w0 = __expf(lrelu(as.x + ad.x, 0.2f) - m0) * i0;
            w1 = __expf(lrelu(as.y + ad.y, 0.2f) - m1) * i1;
            w2 = __expf(lrelu(as.z + ad.z, 0.2f) - m2) * i2;
            w3 = __expf(lrelu(as.w + ad.w, 0.2f) - m3) * i3;
        }
        for (int j = 0; j < rem; j++) {
            int s = __shfl_sync(0xffffffffu, sl, j);
            float a0 = __shfl_sync(0xffffffffu, w0, j);
            float a1 = __shfl_sync(0xffffffffu, w1, j);
            float a2 = __shfl_sync(0xffffffffu, w2, j);
            float a3 = __shfl_sync(0xffffffffu, w3, j);
            const float* hp = hf + (size_t)s * FOUT + lane;
            acc[0] = fmaf(hp[0],   a0, acc[0]);
            acc[1] = fmaf(hp[32],  a0, acc[1]);
            acc[2] = fmaf(hp[64],  a1, acc[2]);
            acc[3] = fmaf(hp[96],  a1, acc[3]);
            acc[4] = fmaf(hp[128], a2, acc[4]);
            acc[5] = fmaf(hp[160], a2, acc[5]);
            acc[6] = fmaf(hp[192], a3, acc[6]);
            acc[7] = fmaf(hp[224], a3, acc[7]);
        }
    }
    float oA = 0.25f * ((acc[0] + acc[2]) + (acc[4] + acc[6])) + bias[lane];
    float oB = 0.25f * ((acc[1] + acc[3]) + (acc[5] + acc[7])) + bias[lane + 32];
    out[(size_t)node * CC + lane]      = lrelu(oA, 0.1f);
    out[(size_t)node * CC + lane + 32] = lrelu(oB, 0.1f);
}

// ---------------------------------------------------------------------------
extern "C" void kernel_launch(void* const* d_in, const int* in_sizes, int n_in,
                              void* d_out, int out_size) {
    const float* x        = (const float*)d_in[0];
    const void*  ei       = d_in[1];
    const float* W1       = (const float*)d_in[2];
    const float* A1       = (const float*)d_in[3];
    const float* att_src1 = (const float*)d_in[4];
    const float* att_dst1 = (const float*)d_in[5];
    const float* b1       = (const float*)d_in[6];
    const float* W2       = (const float*)d_in[7];
    const float* A2       = (const float*)d_in[8];
    const float* att_src2 = (const float*)d_in[9];
    const float* att_dst2 = (const float*)d_in[10];
    const float* b2       = (const float*)d_in[11];
    float* out = (float*)d_out;

    const int n = NN;
    const int eb = (EE + 255) / 256;
    const int nb = (NN + 255) / 256;

    // raw device pointers for globals
    float *p_h, *p_x2, *p_asrc, *p_adst;
    cudaGetSymbolAddress((void**)&p_h, g_h);
    cudaGetSymbolAddress((void**)&p_x2, g_x2);
    cudaGetSymbolAddress((void**)&p_asrc, g_asrc);
    cudaGetSymbolAddress((void**)&p_adst, g_adst);

    // CSR build (replayed each launch; cheap relative to total)
    k_detect<<<1, 32>>>((const int*)ei);
    k_zero_count<<<nb, 256>>>();
    k_hist<<<eb, 256>>>(ei);
    k_scan<<<1, 1024>>>();
    k_scatter<<<eb, 256>>>(ei);

    // ---- layer 1 ----
    k_combine<<<2, 256>>>(A1, att_src1, att_dst1, 128);
    k_gemm<128><<<(n + 31) / 32, 256>>>(x, W1, p_h, p_asrc, p_adst, n);
    k_aggr<<<(n * 32 + 255) / 256, 256>>>(p_h, p_asrc, p_adst, b1, p_x2, n);

    // ---- layer 2 ----
    k_combine<<<1, 256>>>(A2, att_src2, att_dst2, 64);
    k_gemm<64><<<(n + 31) / 32, 256>>>(p_x2, W2, p_h, p_asrc, p_adst, n);
    k_aggr<<<(n * 32 + 255) / 256, 256>>>(p_h, p_asrc, p_adst, b2, out, n);
}

// round 2
// speedup vs baseline: 1.3361x; 1.3361x over previous
#include <cuda_runtime.h>
#include <cuda_bf16.h>
#include <cstdint>

// Problem constants
#define NN   50000
#define EE   800000
#define HH   4
#define CC   64
#define DD   4
#define FOUT 256   // H*C
#define NB2  ((NN + 255) / 256)   // 196 blocks of 256

// ---------------- scratch (device globals; no allocation allowed) ----------
__device__ __align__(16) float g_h[(size_t)NN * FOUT];    // message features [N,256]
__device__ __align__(16) float g_x2[(size_t)NN * CC];     // layer-1 output  [N,64]
__device__ __align__(16) float g_asrc[NN * HH];
__device__ __align__(16) float g_adst[NN * HH];
__device__ __align__(16) float g_vsrc[128 * HH];
__device__ __align__(16) float g_vdst[128 * HH];
__device__ int g_count[NN];
__device__ int g_off[NN];
__device__ int g_rowptr[NN + 1];
__device__ int g_csr[EE];
__device__ int g_is64;
__device__ int g_bsum[256];
__device__ int g_bpre[256];

__device__ __forceinline__ float lrelu(float v, float s) { return v >= 0.f ? v : s * v; }

__device__ __forceinline__ int edge_idx(const void* ei, size_t i, int is64) {
    return is64 ? (int)((const long long*)ei)[i] : ((const int*)ei)[i];
}

// packed f32x2 helpers (sm_103a)
__device__ __forceinline__ unsigned long long pack2(float lo, float hi) {
    unsigned long long r;
    asm("mov.b64 %0, {%1, %2};" : "=l"(r) : "f"(lo), "f"(hi));
    return r;
}
__device__ __forceinline__ void ffma2(unsigned long long& d, unsigned long long a,
                                      unsigned long long b) {
    asm("fma.rn.f32x2 %0, %1, %2, %0;" : "+l"(d) : "l"(a), "l"(b));
}

// ---------------- dtype detection: int64 vs int32 edge_index ---------------
__global__ void k_detect(const int* ei_words) {
    if (threadIdx.x == 0 && blockIdx.x == 0) {
        int nz = 0;
        for (int i = 0; i < 64; i++)
            if (ei_words[2 * i + 1] != 0) nz++;
        g_is64 = (nz == 0) ? 1 : 0;
    }
}

__global__ void k_zero_count() {
    int i = blockIdx.x * blockDim.x + threadIdx.x;
    if (i < NN) g_count[i] = 0;
}

__global__ void k_hist(const void* ei) {
    int e = blockIdx.x * blockDim.x + threadIdx.x;
    if (e >= EE) return;
    int dst = edge_idx(ei, (size_t)EE + e, g_is64);
    atomicAdd(&g_count[dst], 1);
}

// ---- parallel scan: blocksum -> scan of partials -> per-block writeout ----
__global__ __launch_bounds__(256) void k_blocksum() {
    __shared__ int sh[8];
    int i = blockIdx.x * 256 + threadIdx.x;
    int v = (i < NN) ? g_count[i] : 0;
    #pragma unroll
    for (int o = 16; o; o >>= 1) v += __shfl_xor_sync(0xffffffffu, v, o);
    if ((threadIdx.x & 31) == 0) sh[threadIdx.x >> 5] = v;
    __syncthreads();
    if (threadIdx.x == 0) {
        int s = 0;
        #pragma unroll
        for (int j = 0; j < 8; j++) s += sh[j];
        g_bsum[blockIdx.x] = s;
    }
}

__global__ __launch_bounds__(256) void k_scanb(int nb) {
    __shared__ int sh[256];
    int t = threadIdx.x;
    int v = (t < nb) ? g_bsum[t] : 0;
    sh[t] = v;
    __syncthreads();
    for (int o = 1; o < 256; o <<= 1) {
        int u = (t >= o) ? sh[t - o] : 0;
        __syncthreads();
        sh[t] += u;
        __syncthreads();
    }
    if (t < nb) g_bpre[t] = sh[t] - v;  // exclusive
}

__global__ __launch_bounds__(256) void k_writeoff() {
    __shared__ int wpre[8];
    int t = threadIdx.x;
    int lane = t & 31, w = t >> 5;
    int i = blockIdx.x * 256 + t;
    int c = (i < NN) ? g_count[i] : 0;
    int v = c;
    #pragma unroll
    for (int o = 1; o < 32; o <<= 1) {
        int u = __shfl_up_sync(0xffffffffu, v, o);
        if (lane >= o) v += u;
    }
    if (lane == 31) wpre[w] = v;
    __syncthreads();
    if (t == 0) {
        int run = 0;
        #pragma unroll
        for (int j = 0; j < 8; j++) { int tmp = wpre[j]; wpre[j] = run; run += tmp; }
    }
    __syncthreads();
    int excl = v - c + wpre[w] + g_bpre[blockIdx.x];
    if (i < NN) {
        g_rowptr[i] = excl;
        g_off[i] = excl;
        if (i == NN - 1) g_rowptr[NN] = excl + c;
    }
}

__global__ void k_scatter(const void* ei) {
    int e = blockIdx.x * blockDim.x + threadIdx.x;
    if (e >= EE) return;
    int is64 = g_is64;
    int src = edge_idx(ei, (size_t)e, is64);
    int dst = edge_idx(ei, (size_t)EE + e, is64);
    int pos = atomicAdd(&g_off[dst], 1);
    g_csr[pos] = src;
}

// ---------------- combine A with att vectors: vsrc[f,h] = sum_d A[f,h,d]*att_src[h,d]
__global__ void k_combine(const float* __restrict__ A, const float* __restrict__ as,
                          const float* __restrict__ ad, int fin) {
    int t = blockIdx.x * blockDim.x + threadIdx.x;
    if (t < fin * HH) {
        int f = t >> 2, h = t & 3;
        float s1 = 0.f, s2 = 0.f;
        #pragma unroll
        for (int d = 0; d < DD; d++) {
            float a = A[f * (HH * DD) + h * DD + d];
            s1 += a * as[h * DD + d];
            s2 += a * ad[h * DD + d];
        }
        g_vsrc[f * HH + h] = s1;
        g_vdst[f * HH + h] = s2;
    }
}

// ---------------- register-tiled GEMM with packed f32x2 FMA -----------------
// block tile: 64 rows x 256 cols; thread: 8 rows x 8 cols (4 f32x2 col-pairs)
template <int FIN>
__global__ __launch_bounds__(256) void k_gemm(const float* __restrict__ x,
                                              const float* __restrict__ W,
                                              float* __restrict__ hout,
                                              float* __restrict__ asrc,
                                              float* __restrict__ adst, int n) {
    __shared__ float xs[64][FIN + 1];   // +1 pad: conflict-free alpha reads
    __shared__ float ws[8][256];
    int tid = threadIdx.x;
    int tx = tid & 31;      // col group: cols tx*8 .. tx*8+7
    int ty = tid >> 5;      // row group: rows ty*8 .. ty*8+7
    int row0 = blockIdx.x * 64;

    for (int idx = tid; idx < 64 * FIN; idx += 256) {
        int r = idx / FIN, k = idx - r * FIN;
        int row = row0 + r;
        xs[r][k] = (row < n) ? x[(size_t)row * FIN + k] : 0.f;
    }

    unsigned long long acc[8][4];
    #pragma unroll
    for (int r = 0; r < 8; r++)
        #pragma unroll
        for (int j = 0; j < 4; j++) acc[r][j] = 0ull;

    for (int kc = 0; kc < FIN; kc += 8) {
        __syncthreads();   // (first iter: also orders xs writes)
        #pragma unroll
        for (int i = 0; i < 8; i++) ws[i][tid] = W[(size_t)(kc + i) * FOUT + tid];
        __syncthreads();
        #pragma unroll
        for (int kk = 0; kk < 8; kk++) {
            ulonglong2 bA = *(const ulonglong2*)&ws[kk][tx * 8];
            ulonglong2 bB = *(const ulonglong2*)&ws[kk][tx * 8 + 4];
            #pragma unroll
            for (int r = 0; r < 8; r++) {
                float av = xs[ty * 8 + r][kc + kk];   // warp-broadcast
                unsigned long long a2 = pack2(av, av);
                ffma2(acc[r][0], a2, bA.x);
                ffma2(acc[r][1], a2, bA.y);
                ffma2(acc[r][2], a2, bB.x);
                ffma2(acc[r][3], a2, bB.y);
            }
        }
    }

    #pragma unroll
    for (int r = 0; r < 8; r++) {
        int row = row0 + ty * 8 + r;
        if (row < n) {
            ulonglong2* p = (ulonglong2*)&hout[(size_t)row * FOUT + tx * 8];
            p[0] = make_ulonglong2(acc[r][0], acc[r][1]);
            p[1] = make_ulonglong2(acc[r][2], acc[r][3]);
        }
    }

    // alpha: 256 threads = 64 rows x 4 heads; xs padded -> conflict-free
    {
        int r = tid >> 2, h = tid & 3;
        int row = row0 + r;
        if (row < n) {
            float s1 = 0.f, s2 = 0.f;
            #pragma unroll 8
            for (int k = 0; k < FIN; k++) {
                float xv = xs[r][k];
                s1 = fmaf(xv, g_vsrc[k * HH + h], s1);
                s2 = fmaf(xv, g_vdst[k * HH + h], s2);
            }
            asrc[row * HH + h] = s1;
            adst[row * HH + h] = s2;
        }
    }
}

// ---------------- per-dst-node softmax + weighted aggregation (1 warp/node)
// pass 1: max; pass 2 (fused): unnormalized accumulate + denom; scale at end.
__global__ __launch_bounds__(256) void k_aggr(const float* __restrict__ hf,
                                              const float* __restrict__ asrc,
                                              const float* __restrict__ adst,
                                              const float* __restrict__ bias,
                                              float* __restrict__ out, int n) {
    int node = (blockIdx.x * blockDim.x + threadIdx.x) >> 5;
    int lane = threadIdx.x & 31;
    if (node >= n) return;

    int base = g_rowptr[node];
    int deg = g_rowptr[node + 1] - base;

    float4 ad = *(const float4*)(adst + (size_t)node * 4);

    // pass 1: per-head max
    float m0 = -1e30f, m1 = -1e30f, m2 = -1e30f, m3 = -1e30f;
    for (int i = lane; i < deg; i += 32) {
        int s = g_csr[base + i];
        float4 as = *(const float4*)(asrc + (size_t)s * 4);
        m0 = fmaxf(m0, lrelu(as.x + ad.x, 0.2f));
        m1 = fmaxf(m1, lrelu(as.y + ad.y, 0.2f));
        m2 = fmaxf(m2, lrelu(as.z + ad.z, 0.2f));
        m3 = fmaxf(m3, lrelu(as.w + ad.w, 0.2f));
    }
    #pragma unroll
    for (int o = 16; o; o >>= 1) {
        m0 = fmaxf(m0, __shfl_xor_sync(0xffffffffu, m0, o));
        m1 = fmaxf(m1, __shfl_xor_sync(0xffffffffu, m1, o));
        m2 = fmaxf(m2, __shfl_xor_sync(0xffffffffu, m2, o));
        m3 = fmaxf(m3, __shfl_xor_sync(0xffffffffu, m3, o));
    }

    // pass 2 (fused): unnormalized weighted accumulate + denom
    float d0 = 0.f, d1 = 0.f, d2 = 0.f, d3 = 0.f;
    float acc[8] = {0.f, 0.f, 0.f, 0.f, 0.f, 0.f, 0.f, 0.f};
    for (int ib = 0; ib < deg; ib += 32) {
        int rem = min(32, deg - ib);
        int sl = 0;
        float w0 = 0.f, w1 = 0.f, w2 = 0.f, w3 = 0.f;
        if (lane < rem) {
            sl = g_csr[base + ib + lane];
            float4 as = *(const float4*)(asrc + (size_t)sl * 4);
            w0 = __expf(lrelu(as.x + ad.x, 0.2f) - m0);
            w1 = __expf(lrelu(as.y + ad.y, 0.2f) - m1);
            w2 = __expf(lrelu(as.z + ad.z, 0.2f) - m2);
            w3 = __expf(lrelu(as.w + ad.w, 0.2f) - m3);
            d0 += w0; d1 += w1; d2 += w2; d3 += w3;
        }
        for (int j = 0; j < rem; j++) {
            int s = __shfl_sync(0xffffffffu, sl, j);
            float a0 = __shfl_sync(0xffffffffu, w0, j);
            float a1 = __shfl_sync(0xffffffffu, w1, j);
            float a2 = __shfl_sync(0xffffffffu, w2, j);
            float a3 = __shfl_sync(0xffffffffu, w3, j);
            const float* hp = hf + (size_t)s * FOUT + lane;
            acc[0] = fmaf(hp[0],   a0, acc[0]);
            acc[1] = fmaf(hp[32],  a0, acc[1]);
            acc[2] = fmaf(hp[64],  a1, acc[2]);
            acc[3] = fmaf(hp[96],  a1, acc[3]);
            acc[4] = fmaf(hp[128], a2, acc[4]);
            acc[5] = fmaf(hp[160], a2, acc[5]);
            acc[6] = fmaf(hp[192], a3, acc[6]);
            acc[7] = fmaf(hp[224], a3, acc[7]);
        }
    }
    #pragma unroll
    for (int o = 16; o; o >>= 1) {
        d0 += __shfl_xor_sync(0xffffffffu, d0, o);
        d1 += __shfl_xor_sync(0xffffffffu, d1, o);
        d2 += __shfl_xor_sync(0xffffffffu, d2, o);
        d3 += __shfl_xor_sync(0xffffffffu, d3, o);
    }
    float i0 = d0 > 0.f ? 0.25f / d0 : 0.f;
    float i1 = d1 > 0.f ? 0.25f / d1 : 0.f;
    float i2 = d2 > 0.f ? 0.25f / d2 : 0.f;
    float i3 = d3 > 0.f ? 0.25f / d3 : 0.f;

    float oA = acc[0] * i0 + acc[2] * i1 + acc[4] * i2 + acc[6] * i3 + bias[lane];
    float oB = acc[1] * i0 + acc[3] * i1 + acc[5] * i2 + acc[7] * i3 + bias[lane + 32];
    out[(size_t)node * CC + lane]      = lrelu(oA, 0.1f);
    out[(size_t)node * CC + lane + 32] = lrelu(oB, 0.1f);
}

// ---------------------------------------------------------------------------
extern "C" void kernel_launch(void* const* d_in, const int* in_sizes, int n_in,
                              void* d_out, int out_size) {
    const float* x        = (const float*)d_in[0];
    const void*  ei       = d_in[1];
    const float* W1       = (const float*)d_in[2];
    const float* A1       = (const float*)d_in[3];
    const float* att_src1 = (const float*)d_in[4];
    const float* att_dst1 = (const float*)d_in[5];
    const float* b1       = (const float*)d_in[6];
    const float* W2       = (const float*)d_in[7];
    const float* A2       = (const float*)d_in[8];
    const float* att_src2 = (const float*)d_in[9];
    const float* att_dst2 = (const float*)d_in[10];
    const float* b2       = (const float*)d_in[11];
    float* out = (float*)d_out;

    const int n = NN;
    const int eb = (EE + 255) / 256;

    float *p_h, *p_x2, *p_asrc, *p_adst;
    cudaGetSymbolAddress((void**)&p_h, g_h);
    cudaGetSymbolAddress((void**)&p_x2, g_x2);
    cudaGetSymbolAddress((void**)&p_asrc, g_asrc);
    cudaGetSymbolAddress((void**)&p_adst, g_adst);

    // CSR build (parallel scan)
    k_detect<<<1, 32>>>((const int*)ei);
    k_zero_count<<<NB2, 256>>>();
    k_hist<<<eb, 256>>>(ei);
    k_blocksum<<<NB2, 256>>>();
    k_scanb<<<1, 256>>>(NB2);
    k_writeoff<<<NB2, 256>>>();
    k_scatter<<<eb, 256>>>(ei);

    // ---- layer 1 ----
    k_combine<<<2, 256>>>(A1, att_src1, att_dst1, 128);
    k_gemm<128><<<(n + 63) / 64, 256>>>(x, W1, p_h, p_asrc, p_adst, n);
    k_aggr<<<(n * 32 + 255) / 256, 256>>>(p_h, p_asrc, p_adst, b1, p_x2, n);

    // ---- layer 2 ----
    k_combine<<<1, 256>>>(A2, att_src2, att_dst2, 64);
    k_gemm<64><<<(n + 63) / 64, 256>>>(p_x2, W2, p_h, p_asrc, p_adst, n);
    k_aggr<<<(n * 32 + 255) / 256, 256>>>(p_h, p_asrc, p_adst, b2, out, n);
}